// round 3
// baseline (speedup 1.0000x reference)
#include <cuda_runtime.h>

#define TPB    256
#define NBINS  64
#define SBINS  56          // max reachable bin = ceil(31.5*sqrt(3)) = 55
#define NPTS   4096
#define GRID   296         // 148 SMs * 2 CTAs/SM
#define NUNITS 2048        // row-pairs (u, n-1-u): each exactly 4095 pairs

// Scratch (allocation-free __device__ globals). Invariant: zero at entry of
// every launch; the finalizing block resets them for graph replay.
__device__ int      g_hist[NBINS];
__device__ unsigned g_done = 0;

extern __shared__ float smem_raw[];
// layout: sx[4096] | sy[4096] | sz[4096] | hist u32[56][256]

__global__ __launch_bounds__(TPB, 2)
void ecc_kernel(const float* __restrict__ x, float* __restrict__ out, int n) {
    float* sx = smem_raw;
    float* sy = smem_raw + NPTS;
    float* sz = smem_raw + 2 * NPTS;
    unsigned* sh = (unsigned*)(smem_raw + 3 * NPTS);

    const int tid = threadIdx.x;

    // Zero private histograms
    #pragma unroll
    for (int k = 0; k < SBINS; k++) sh[k * TPB + tid] = 0u;

    // Stage points planar: 4 points = 3 float4 reads -> 3 float4 smem stores
    const float4* x4 = (const float4*)x;
    for (int g = tid; g < NPTS / 4; g += TPB) {
        const float4 a = x4[3 * g + 0];
        const float4 b = x4[3 * g + 1];
        const float4 c = x4[3 * g + 2];
        ((float4*)sx)[g] = make_float4(a.x, a.w, b.z, c.y);
        ((float4*)sy)[g] = make_float4(a.y, b.x, b.w, c.z);
        ((float4*)sz)[g] = make_float4(a.z, b.y, c.x, c.w);
    }
    __syncthreads();

    unsigned* myh = sh + tid;   // per-thread column: bank tid%32, conflict-free

    // Units (u, n-1-u): 4095 pairs each -> near-perfect balance at GRID=296
    for (int u = blockIdx.x; u < NUNITS; u += GRID) {
        int rows[2];
        rows[0] = u;
        rows[1] = n - 1 - u;
        #pragma unroll
        for (int rr = 0; rr < 2; rr++) {
            const int i = rows[rr];
            const float pix = sx[i];     // LDS broadcast
            const float piy = sy[i];
            const float piz = sz[i];
            #pragma unroll 4
            for (int j = i + 1 + tid; j < n; j += TPB) {
                const float dx = pix - sx[j];
                const float dy = piy - sy[j];
                const float dz = piz - sz[j];
                const float s  = dx * dx + dy * dy + dz * dz;  // FMA ok (tol 1e-3)
                float r;
                asm("rsqrt.approx.f32 %0, %1;" : "=f"(r) : "f"(s));
                // bin = ceil(31.5 * d); s==0 -> 0*inf=NaN -> F2I gives 0 (= ref)
                int b = __float2int_ru(31.5f * s * r);
                b = min(b, SBINS - 1);          // guards inf/saturation
                myh[b * TPB] += 1u;
            }
        }
    }
    __syncthreads();

    // Block-reduce [56][256] -> g_hist: 4 threads/bin, rotated conflict-free
    if (tid < SBINS * 4) {
        const int b = tid >> 2;
        const int q = tid & 3;
        unsigned sum = 0;
        #pragma unroll 8
        for (int c = 0; c < 64; c++)
            sum += sh[b * TPB + q * 64 + ((c + tid) & 63)];
        sum += __shfl_xor_sync(0xffffffffu, sum, 1);
        sum += __shfl_xor_sync(0xffffffffu, sum, 2);
        if (q == 0) atomicAdd(&g_hist[b], (int)sum);
    }
    __syncthreads();

    // Last-block-done: the final block scans, writes out, resets scratch
    __shared__ unsigned s_last;
    if (tid == 0) {
        __threadfence();
        s_last = (atomicAdd(&g_done, 1u) == (unsigned)gridDim.x - 1u);
    }
    __syncthreads();
    if (s_last && tid == 0) {
        float acc = 0.0f;
        #pragma unroll
        for (int k = 0; k < NBINS; k++) {
            const int h = atomicAdd(&g_hist[k], 0);   // L2-coherent read
            float v = -(float)h;
            if (k == 0) v += (float)n;                // +n vertices at filt 0
            acc += v;
            out[k] = acc;
            g_hist[k] = 0;                            // reset for next replay
        }
        g_done = 0;
    }
}

extern "C" void kernel_launch(void* const* d_in, const int* in_sizes, int n_in,
                              void* d_out, int out_size) {
    const float* x = (const float*)d_in[0];
    float* out = (float*)d_out;
    const int n = in_sizes[0] / 3;   // 4096

    const int smem = (3 * NPTS + SBINS * TPB) * (int)sizeof(float);  // 106496
    cudaFuncSetAttribute(ecc_kernel,
                         cudaFuncAttributeMaxDynamicSharedMemorySize, smem);
    ecc_kernel<<<GRID, TPB, smem>>>(x, out, n);
}

// round 4
// speedup vs baseline: 1.0525x; 1.0525x over previous
#include <cuda_runtime.h>

#define TPB    256
#define NBINS  64
#define SBINS  56          // max reachable bin = ceil(31.5*sqrt(3)) = 55
#define NPTS   4096
#define NGRP   1024        // NPTS / 4
#define GRID   444         // 148 SMs * 3 CTAs/SM
#define NUNITS 2048        // row-pairs (u, n-1-u): each exactly 4095 pairs

// Scratch (allocation-free __device__ globals). Zero at entry of every
// launch; the finalizing block resets them (graph-replay safe).
__device__ int      g_hist[NBINS];
__device__ unsigned g_done = 0;

__device__ __forceinline__ int pair_bin(float dx, float dy, float dz) {
    const float s = dx * dx + dy * dy + dz * dz;   // FMA contraction ok (tol 1e-3)
    float r;
    asm("rsqrt.approx.f32 %0, %1;" : "=f"(r) : "f"(s));
    int b = __float2int_ru(31.5f * (s * r));       // ceil(31.5*d); NaN -> 0
    return min(b, SBINS - 1);
}

__global__ __launch_bounds__(TPB, 3)
void ecc_kernel(const float* __restrict__ x, float* __restrict__ out, int n) {
    __shared__ unsigned sh[SBINS * TPB];   // [bin][256]: column tid -> bank tid%32

    const int tid = threadIdx.x;
    unsigned* myh = sh + tid;

    #pragma unroll
    for (int k = 0; k < SBINS; k++) myh[k * TPB] = 0u;
    __syncthreads();

    const float4* __restrict__ x4 = (const float4*)x;

    for (int u = blockIdx.x; u < NUNITS; u += GRID) {
        int rows[2];
        rows[0] = u;
        rows[1] = n - 1 - u;
        #pragma unroll
        for (int rr = 0; rr < 2; rr++) {
            const int i   = rows[rr];
            const float pix = __ldg(&x[3 * i + 0]);
            const float piy = __ldg(&x[3 * i + 1]);
            const float piz = __ldg(&x[3 * i + 2]);

            const int g0   = (i + 4) >> 2;          // first full float4 group
            const int head = 4 * g0 - (i + 1);      // 0..3 leading pairs

            if (tid < head) {
                const int j = i + 1 + tid;
                const int b = pair_bin(pix - __ldg(&x[3 * j + 0]),
                                       piy - __ldg(&x[3 * j + 1]),
                                       piz - __ldg(&x[3 * j + 2]));
                myh[b * TPB] += 1u;
            }

            // Body: 4 j-points per iteration = 3 aligned float4 loads
            #pragma unroll 2
            for (int g = g0 + tid; g < NGRP; g += TPB) {
                const float4 a = __ldg(&x4[3 * g + 0]);
                const float4 q = __ldg(&x4[3 * g + 1]);
                const float4 c = __ldg(&x4[3 * g + 2]);
                const int b0 = pair_bin(pix - a.x, piy - a.y, piz - a.z);
                const int b1 = pair_bin(pix - a.w, piy - q.x, piz - q.y);
                const int b2 = pair_bin(pix - q.z, piy - q.w, piz - c.x);
                const int b3 = pair_bin(pix - c.y, piy - c.z, piz - c.w);
                myh[b0 * TPB] += 1u;
                myh[b1 * TPB] += 1u;
                myh[b2 * TPB] += 1u;
                myh[b3 * TPB] += 1u;
            }
        }
    }
    __syncthreads();

    // Block-reduce [56][256] -> g_hist: 4 threads/bin, rotated (conflict-free)
    if (tid < SBINS * 4) {
        const int b = tid >> 2;
        const int q = tid & 3;
        unsigned sum = 0;
        #pragma unroll 8
        for (int c = 0; c < 64; c++)
            sum += sh[b * TPB + q * 64 + ((c + tid) & 63)];
        sum += __shfl_xor_sync(0xffffffffu, sum, 1);
        sum += __shfl_xor_sync(0xffffffffu, sum, 2);
        if (q == 0) atomicAdd(&g_hist[b], (int)sum);
    }
    __syncthreads();

    // Last-done block: scan 64 bins, write out, reset scratch
    __shared__ unsigned s_last;
    if (tid == 0) {
        __threadfence();
        s_last = (atomicAdd(&g_done, 1u) == (unsigned)gridDim.x - 1u);
    }
    __syncthreads();
    if (s_last && tid == 0) {
        float acc = 0.0f;
        #pragma unroll
        for (int k = 0; k < NBINS; k++) {
            const int h = atomicAdd(&g_hist[k], 0);  // coherent read
            float v = -(float)h;
            if (k == 0) v += (float)n;               // +n vertices at filt 0
            acc += v;
            out[k] = acc;
            g_hist[k] = 0;
        }
        g_done = 0;
    }
}

extern "C" void kernel_launch(void* const* d_in, const int* in_sizes, int n_in,
                              void* d_out, int out_size) {
    const float* x = (const float*)d_in[0];
    float* out = (float*)d_out;
    const int n = in_sizes[0] / 3;   // 4096
    ecc_kernel<<<GRID, TPB>>>(x, out, n);
}